// round 7
// baseline (speedup 1.0000x reference)
#include <cuda_runtime.h>

#define N_NODES 50000
#define N_EDGES 800000
#define HIDDEN 64
#define NODE_DIM 32
#define EDGE_DIM 16
#define CAP 96

// acc rows per node (80 floats): [0:16)=sum(ef), [16:80)=sum(h[src])
// Two partial buffers (one per gather sub-warp); fused kernel sums them.
__device__ __align__(16) float g_acc [(size_t)N_NODES * 80];
__device__ __align__(16) float g_acc2[(size_t)N_NODES * 80];
__device__ int   g_count[N_NODES];
__device__ int   g_ovf_cnt;
__device__ __align__(8) int2 g_ell[(size_t)N_NODES * CAP];
__device__ int3  g_ovf[N_EDGES];

typedef unsigned long long u64;

__device__ __forceinline__ void fma2(u64& d, u64 a, u64 b) {
    asm("fma.rn.f32x2 %0, %1, %2, %0;" : "+l"(d) : "l"(a), "l"(b));
}
__device__ __forceinline__ u64 rep2(float x) {
    u64 r;
    asm("mov.b64 %0, {%1, %1};" : "=l"(r) : "f"(x));
    return r;
}
__device__ __forceinline__ float2 unpack2(u64 v) {
    float2 p;
    asm("mov.b64 {%0, %1}, %2;" : "=f"(p.x), "=f"(p.y) : "l"(v));
    return p;
}

// ---------------------------------------------------------------------------
__global__ void zero_kernel() {
    int i = blockIdx.x * blockDim.x + threadIdx.x;
    const int CNT4 = N_NODES / 4;
    if (i < CNT4) reinterpret_cast<int4*>(g_count)[i] = make_int4(0, 0, 0, 0);
    if (i == 0) g_ovf_cnt = 0;
}

// ---------------------------------------------------------------------------
__global__ void __launch_bounds__(256) scatter_kernel(
    const int* __restrict__ src, const int* __restrict__ dst)
{
    int e = blockIdx.x * 256 + threadIdx.x;
    if (e >= N_EDGES) return;
    int d = dst[e];
    int s = src[e];
    int pos = atomicAdd(&g_count[d], 1);
    if (pos < CAP) {
        g_ell[(size_t)d * CAP + pos] = make_int2(s, e);
    } else {
        int o = atomicAdd(&g_ovf_cnt, 1);
        g_ovf[o] = make_int3(d, s, e);
    }
}

// ---------------------------------------------------------------------------
// Gather: TWO warps per node, striding the ELL list by 2. Each warp writes an
// independent partial (g_acc / g_acc2) with plain STG — no atomics, no zeroing.
// Lanes 0-3: ef float4 chunks; lanes 4-19: h float4 chunks.
// ---------------------------------------------------------------------------
__device__ __forceinline__ void acc_edge(
    float4& a, int l, int s, int e,
    const float* __restrict__ h, const float* __restrict__ ef)
{
    if (l < 20) {
        const float* p = (l < 4)
            ? (ef + (size_t)e * EDGE_DIM + l * 4)
            : (h  + (size_t)s * HIDDEN + (l - 4) * 4);
        float4 v = *reinterpret_cast<const float4*>(p);
        a.x += v.x; a.y += v.y; a.z += v.z; a.w += v.w;
    }
}

__global__ void __launch_bounds__(256) gather_kernel(
    const float* __restrict__ h, const float* __restrict__ ef)
{
    int gw  = (blockIdx.x * 256 + threadIdx.x) >> 5;   // global warp
    int n   = gw >> 1;
    int sub = gw & 1;
    int l   = threadIdx.x & 31;
    if (n >= N_NODES) return;
    int cnt_raw = g_count[n];
    if (cnt_raw == 0) return;
    int cnt = min(cnt_raw, CAP);

    float4 a = make_float4(0.f, 0.f, 0.f, 0.f);
    const int2* __restrict__ eb = g_ell + (size_t)n * CAP;

    int j = sub;
    for (; j + 6 < cnt; j += 8) {
        int2 e0 = eb[j], e1 = eb[j + 2], e2 = eb[j + 4], e3 = eb[j + 6];
        acc_edge(a, l, e0.x, e0.y, h, ef);
        acc_edge(a, l, e1.x, e1.y, h, ef);
        acc_edge(a, l, e2.x, e2.y, h, ef);
        acc_edge(a, l, e3.x, e3.y, h, ef);
    }
    for (; j < cnt; j += 2) {
        int2 e = eb[j];
        acc_edge(a, l, e.x, e.y, h, ef);
    }
    if (sub == 0 && cnt_raw > CAP) {   // exact fallback; practically never taken
        int ovf = g_ovf_cnt;
        for (int i = 0; i < ovf; i++) {
            int3 t = g_ovf[i];
            if (t.x == n) acc_edge(a, l, t.y, t.z, h, ef);
        }
    }
    if (l < 20) {
        float* dstp = (sub ? g_acc2 : g_acc) + (size_t)n * 80 + l * 4;
        *reinterpret_cast<float4*>(dstp) = a;
    }
}

// ---------------------------------------------------------------------------
// Fused node kernel (128 threads, 4x16 microtile, f32x2 FMAs):
//   phase 1: Y = relu(Z @ W1^T), K=144, Z assembled on the fly (acc+acc2)
//   phase 2: O = Y @ W2^T, K=64
// Smem 48KB: Yt ALIASES At+Bt (live ranges disjoint, separated by barriers)
//   [0 .. 8192)     At[16][128] (2048) | Bt[16][64] (1024)   /   Yt[64][128]
//   [8192 .. 12288) W2t[64][64]
// => 4 CTAs/SM, grid 391 fully resident in one wave.
// ---------------------------------------------------------------------------
#define FUSED_SMEM_FLOATS 12288   // 49,152 bytes

__global__ void __launch_bounds__(128) fused_node_kernel(
    const float* __restrict__ h, const float* __restrict__ nf,
    const float* __restrict__ W1, const float* __restrict__ W2,
    float* __restrict__ out)
{
    extern __shared__ float sm[];
    float* At  = sm;                // [16][128]
    float* Bt  = sm + 2048;         // [16][64]
    float* Yt  = sm;                // [64][128]  (aliases At+Bt)
    float* W2t = sm + 8192;         // [64][64]

    const int tid  = threadIdx.x;
    const int tx   = tid & 31;
    const int ty   = tid >> 5;
    const int base = blockIdx.x * 128;

    // one-time: W2 -> W2t[k][n] (read only in phase 2, after barriers)
    {
        int n = tid & 63, half = tid >> 6;
        #pragma unroll
        for (int r = 0; r < 8; r++) {
            int kf4 = half + r * 2;
            float4 v = *reinterpret_cast<const float4*>(W2 + (size_t)n * 64 + kf4 * 4);
            W2t[(kf4 * 4 + 0) * 64 + n] = v.x;
            W2t[(kf4 * 4 + 1) * 64 + n] = v.y;
            W2t[(kf4 * 4 + 2) * 64 + n] = v.z;
            W2t[(kf4 * 4 + 3) * 64 + n] = v.w;
        }
    }

    u64 accP[4][8];
#pragma unroll
    for (int i = 0; i < 4; i++)
#pragma unroll
        for (int j = 0; j < 8; j++) accP[i][j] = 0ull;

    const int nrow = base + tid;
    const bool valid = (nrow < N_NODES);
    const float degf = valid ? (float)g_count[nrow] : 0.f;

    // ======================= phase 1: K = 144 =======================
    for (int kc = 0; kc < 9; kc++) {
        const int k0 = kc * 16;
        if (kc > 0) __syncthreads();

        #pragma unroll
        for (int kg = 0; kg < 4; kg++) {
            int gk = k0 + kg * 4;
            float4 v = make_float4(0.f, 0.f, 0.f, 0.f);
            if (valid) {
                if (gk < 32) {
                    v = *reinterpret_cast<const float4*>(nf + (size_t)nrow * 32 + gk);
                } else if (gk < 64) {
                    v = *reinterpret_cast<const float4*>(nf + (size_t)nrow * 32 + gk - 32);
                    v.x *= degf; v.y *= degf; v.z *= degf; v.w *= degf;
                } else {
                    size_t off = (size_t)nrow * 80 +
                                 ((gk < 80) ? (gk - 64) : (16 + (gk - 80)));
                    float4 p0 = *reinterpret_cast<const float4*>(g_acc  + off);
                    float4 p1 = *reinterpret_cast<const float4*>(g_acc2 + off);
                    v = make_float4(p0.x + p1.x, p0.y + p1.y,
                                    p0.z + p1.z, p0.w + p1.w);
                }
            }
            At[(kg * 4 + 0) * 128 + tid] = v.x;
            At[(kg * 4 + 1) * 128 + tid] = v.y;
            At[(kg * 4 + 2) * 128 + tid] = v.z;
            At[(kg * 4 + 3) * 128 + tid] = v.w;
        }
        {
            int n = tid & 63, kp = tid >> 6;
            #pragma unroll
            for (int rr = 0; rr < 2; rr++) {
                int kg = kp * 2 + rr;
                float4 v = *reinterpret_cast<const float4*>(W1 + (size_t)n * 144 + k0 + kg * 4);
                Bt[(kg * 4 + 0) * 64 + n] = v.x;
                Bt[(kg * 4 + 1) * 64 + n] = v.y;
                Bt[(kg * 4 + 2) * 64 + n] = v.z;
                Bt[(kg * 4 + 3) * 64 + n] = v.w;
            }
        }
        __syncthreads();

        #pragma unroll
        for (int kk = 0; kk < 16; kk++) {
            float a[4];
            #pragma unroll
            for (int i = 0; i < 4; i++) a[i] = At[kk * 128 + tx + 32 * i];
            u64 b[8];
            #pragma unroll
            for (int j2 = 0; j2 < 8; j2++)
                b[j2] = *reinterpret_cast<const u64*>(&Bt[kk * 64 + ty * 16 + j2 * 2]);
            #pragma unroll
            for (int i = 0; i < 4; i++) {
                u64 ar = rep2(a[i]);
                #pragma unroll
                for (int j2 = 0; j2 < 8; j2++) fma2(accP[i][j2], ar, b[j2]);
            }
        }
    }

    // relu -> Yt[k][m] (Yt aliases At/Bt: barrier separates last reads from writes)
    __syncthreads();
#pragma unroll
    for (int i = 0; i < 4; i++)
#pragma unroll
        for (int j2 = 0; j2 < 8; j2++) {
            float2 p = unpack2(accP[i][j2]);
            Yt[(ty * 16 + j2 * 2 + 0) * 128 + tx + 32 * i] = fmaxf(p.x, 0.f);
            Yt[(ty * 16 + j2 * 2 + 1) * 128 + tx + 32 * i] = fmaxf(p.y, 0.f);
            accP[i][j2] = 0ull;
        }
    __syncthreads();

    // ======================= phase 2: K = 64 =======================
#pragma unroll 8
    for (int kk = 0; kk < 64; kk++) {
        float a[4];
        #pragma unroll
        for (int i = 0; i < 4; i++) a[i] = Yt[kk * 128 + tx + 32 * i];
        u64 b[8];
        #pragma unroll
        for (int j2 = 0; j2 < 8; j2++)
            b[j2] = *reinterpret_cast<const u64*>(&W2t[kk * 64 + ty * 16 + j2 * 2]);
        #pragma unroll
        for (int i = 0; i < 4; i++) {
            u64 ar = rep2(a[i]);
            #pragma unroll
            for (int j2 = 0; j2 < 8; j2++) fma2(accP[i][j2], ar, b[j2]);
        }
    }

    // ---- epilogue ----
#pragma unroll
    for (int i = 0; i < 4; i++) {
        int n = base + tx + 32 * i;
        if (n >= N_NODES) continue;
        bool has = (g_count[n] > 0);
        #pragma unroll
        for (int half = 0; half < 2; half++) {
            #pragma unroll
            for (int q = 0; q < 2; q++) {
                int jb = half * 4 + q * 2;
                float4 w;
                if (has) {
                    float2 p0 = unpack2(accP[i][jb + 0]);
                    float2 p1 = unpack2(accP[i][jb + 1]);
                    w = make_float4(p0.x, p0.y, p1.x, p1.y);
                } else {
                    w = *reinterpret_cast<const float4*>(
                        h + (size_t)n * HIDDEN + ty * 16 + half * 8 + q * 4);
                }
                *reinterpret_cast<float4*>(
                    out + (size_t)n * HIDDEN + ty * 16 + half * 8 + q * 4) = w;
            }
        }
    }
}

// ---------------------------------------------------------------------------
extern "C" void kernel_launch(void* const* d_in, const int* in_sizes, int n_in,
                              void* d_out, int out_size)
{
    const float* h   = (const float*)d_in[0];
    const float* nf  = (const float*)d_in[1];
    const float* ef  = (const float*)d_in[2];
    const int*   src = (const int*)d_in[3];
    const int*   dst = (const int*)d_in[4];
    const float* W1  = (const float*)d_in[5];
    const float* W2  = (const float*)d_in[6];
    float*       out = (float*)d_out;

    zero_kernel<<<(N_NODES / 4 + 255) / 256, 256>>>();
    scatter_kernel<<<(N_EDGES + 255) / 256, 256>>>(src, dst);

    const int gwarps = N_NODES * 2;                      // 2 warps per node
    gather_kernel<<<(gwarps * 32 + 255) / 256, 256>>>(h, ef);

    cudaFuncSetAttribute(fused_node_kernel,
                         cudaFuncAttributeMaxDynamicSharedMemorySize,
                         FUSED_SMEM_FLOATS * sizeof(float));
    const int blocks = (N_NODES + 127) / 128;            // 391
    fused_node_kernel<<<blocks, 128, FUSED_SMEM_FLOATS * sizeof(float)>>>(
        h, nf, W1, W2, out);
}

// round 8
// speedup vs baseline: 1.0805x; 1.0805x over previous
#include <cuda_runtime.h>

#define N_NODES 50000
#define N_EDGES 800000
#define HIDDEN 64
#define NODE_DIM 32
#define EDGE_DIM 16
#define CAP 96

// acc row per node (80 floats): [0:16)=sum(ef), [16:80)=sum(h[src])
__device__ __align__(16) float g_acc[(size_t)N_NODES * 80];
__device__ int   g_count[N_NODES];
__device__ int   g_ovf_cnt;
__device__ __align__(8) int2 g_ell[(size_t)N_NODES * CAP];
__device__ int3  g_ovf[N_EDGES];

typedef unsigned long long u64;

__device__ __forceinline__ void fma2(u64& d, u64 a, u64 b) {
    asm("fma.rn.f32x2 %0, %1, %2, %0;" : "+l"(d) : "l"(a), "l"(b));
}
__device__ __forceinline__ u64 rep2(float x) {
    u64 r;
    asm("mov.b64 %0, {%1, %1};" : "=l"(r) : "f"(x));
    return r;
}
__device__ __forceinline__ float2 unpack2(u64 v) {
    float2 p;
    asm("mov.b64 {%0, %1}, %2;" : "=f"(p.x), "=f"(p.y) : "l"(v));
    return p;
}

// ---------------------------------------------------------------------------
__global__ void zero_kernel() {
    int i = blockIdx.x * blockDim.x + threadIdx.x;
    const int CNT4 = N_NODES / 4;
    if (i < CNT4) reinterpret_cast<int4*>(g_count)[i] = make_int4(0, 0, 0, 0);
    if (i == 0) g_ovf_cnt = 0;
}

// ---------------------------------------------------------------------------
__global__ void __launch_bounds__(256) scatter_kernel(
    const int* __restrict__ src, const int* __restrict__ dst)
{
    int e = blockIdx.x * 256 + threadIdx.x;
    if (e >= N_EDGES) return;
    int d = dst[e];
    int s = src[e];
    int pos = atomicAdd(&g_count[d], 1);
    if (pos < CAP) {
        g_ell[(size_t)d * CAP + pos] = make_int2(s, e);
    } else {
        int o = atomicAdd(&g_ovf_cnt, 1);
        g_ovf[o] = make_int3(d, s, e);
    }
}

// ---------------------------------------------------------------------------
// Warp-per-node gather (Round-5 version). ELL entries fetched with
// warp-uniform broadcast LDG, unrolled x4 for MLP.
// Lanes 0-3: ef float4 chunks; lanes 4-19: h float4 chunks. Plain STG out.
// ---------------------------------------------------------------------------
__device__ __forceinline__ void acc_edge(
    float4& a, int l, int s, int e,
    const float* __restrict__ h, const float* __restrict__ ef)
{
    if (l < 20) {
        const float* p = (l < 4)
            ? (ef + (size_t)e * EDGE_DIM + l * 4)
            : (h  + (size_t)s * HIDDEN + (l - 4) * 4);
        float4 v = *reinterpret_cast<const float4*>(p);
        a.x += v.x; a.y += v.y; a.z += v.z; a.w += v.w;
    }
}

__global__ void __launch_bounds__(256) gather_kernel(
    const float* __restrict__ h, const float* __restrict__ ef)
{
    int n = (blockIdx.x * 256 + threadIdx.x) >> 5;
    int l = threadIdx.x & 31;
    if (n >= N_NODES) return;
    int cnt_raw = g_count[n];
    if (cnt_raw == 0) return;
    int cnt = min(cnt_raw, CAP);

    float4 a = make_float4(0.f, 0.f, 0.f, 0.f);
    const int2* __restrict__ eb = g_ell + (size_t)n * CAP;

    int j = 0;
    for (; j + 4 <= cnt; j += 4) {
        int2 e0 = eb[j], e1 = eb[j + 1], e2 = eb[j + 2], e3 = eb[j + 3];
        acc_edge(a, l, e0.x, e0.y, h, ef);
        acc_edge(a, l, e1.x, e1.y, h, ef);
        acc_edge(a, l, e2.x, e2.y, h, ef);
        acc_edge(a, l, e3.x, e3.y, h, ef);
    }
    for (; j < cnt; j++) {
        int2 e = eb[j];
        acc_edge(a, l, e.x, e.y, h, ef);
    }
    if (cnt_raw > CAP) {   // exact fallback; practically never taken
        int ovf = g_ovf_cnt;
        for (int i = 0; i < ovf; i++) {
            int3 t = g_ovf[i];
            if (t.x == n) acc_edge(a, l, t.y, t.z, h, ef);
        }
    }
    if (l < 20)
        *reinterpret_cast<float4*>(g_acc + (size_t)n * 80 + l * 4) = a;
}

// ---------------------------------------------------------------------------
// Fused node kernel — 256 threads, M=128 tile, 2x16 microtile, f32x2 FMAs.
//   phase 1: Y = relu(Z @ W1^T), K=144, Z assembled on the fly
//   phase 2: O = Y @ W2^T, K=64
// Warp w: rows (w>>2)*64 + tx + 32*i (i<2), cols (w&3)*16.
// Smem 48KB (Yt aliases At+Bt):
//   [0..8192)  At[16][128] | Bt[16][64]   /   Yt[64][128]
//   [8192..12288) W2t[64][64]
// ---------------------------------------------------------------------------
#define FUSED_SMEM_FLOATS 12288   // 49,152 bytes

__global__ void __launch_bounds__(256) fused_node_kernel(
    const float* __restrict__ h, const float* __restrict__ nf,
    const float* __restrict__ W1, const float* __restrict__ W2,
    float* __restrict__ out)
{
    extern __shared__ float sm[];
    float* At  = sm;                // [16][128]
    float* Bt  = sm + 2048;         // [16][64]
    float* Yt  = sm;                // [64][128] (aliases At+Bt)
    float* W2t = sm + 8192;         // [64][64]

    const int tid   = threadIdx.x;
    const int tx    = tid & 31;
    const int w     = tid >> 5;          // warp 0..7
    const int rh    = (w >> 2) * 64;     // row half offset
    const int cb    = (w & 3) * 16;      // col base
    const int base  = blockIdx.x * 128;

    // one-time: W2 -> W2t[k][n] (read only in phase 2)
    {
        int n = tid & 63, kp = tid >> 6;          // kp in 0..3
        #pragma unroll
        for (int r = 0; r < 4; r++) {
            int kf4 = kp + r * 4;                 // 0..15
            float4 v = *reinterpret_cast<const float4*>(W2 + (size_t)n * 64 + kf4 * 4);
            W2t[(kf4 * 4 + 0) * 64 + n] = v.x;
            W2t[(kf4 * 4 + 1) * 64 + n] = v.y;
            W2t[(kf4 * 4 + 2) * 64 + n] = v.z;
            W2t[(kf4 * 4 + 3) * 64 + n] = v.w;
        }
    }

    u64 accP[2][8];
#pragma unroll
    for (int i = 0; i < 2; i++)
#pragma unroll
        for (int j = 0; j < 8; j++) accP[i][j] = 0ull;

    // A-loader role: row rowA, k-group pair kpA
    const int rowA = tid & 127;
    const int kpA  = tid >> 7;            // 0 or 1
    const int nrow = base + rowA;
    const bool valid = (nrow < N_NODES);
    const float degf = valid ? (float)g_count[nrow] : 0.f;

    // ======================= phase 1: K = 144 =======================
    for (int kc = 0; kc < 9; kc++) {
        const int k0 = kc * 16;
        if (kc > 0) __syncthreads();

        // A tile: each thread loads 2 float4 of Z[rowA][k0 + kpA*8 .. +7]
        #pragma unroll
        for (int kg = 0; kg < 2; kg++) {
            int g4 = kpA * 2 + kg;        // 0..3
            int gk = k0 + g4 * 4;
            float4 v = make_float4(0.f, 0.f, 0.f, 0.f);
            if (valid) {
                if (gk < 32) {
                    v = *reinterpret_cast<const float4*>(nf + (size_t)nrow * 32 + gk);
                } else if (gk < 64) {
                    v = *reinterpret_cast<const float4*>(nf + (size_t)nrow * 32 + gk - 32);
                    v.x *= degf; v.y *= degf; v.z *= degf; v.w *= degf;
                } else {
                    size_t off = (size_t)nrow * 80 +
                                 ((gk < 80) ? (gk - 64) : (16 + (gk - 80)));
                    v = *reinterpret_cast<const float4*>(g_acc + off);
                }
            }
            At[(g4 * 4 + 0) * 128 + rowA] = v.x;
            At[(g4 * 4 + 1) * 128 + rowA] = v.y;
            At[(g4 * 4 + 2) * 128 + rowA] = v.z;
            At[(g4 * 4 + 3) * 128 + rowA] = v.w;
        }
        // B tile: W1[n][k0..k0+15], 1 float4 per thread
        {
            int n = tid & 63, kg = tid >> 6;      // kg 0..3
            float4 v = *reinterpret_cast<const float4*>(W1 + (size_t)n * 144 + k0 + kg * 4);
            Bt[(kg * 4 + 0) * 64 + n] = v.x;
            Bt[(kg * 4 + 1) * 64 + n] = v.y;
            Bt[(kg * 4 + 2) * 64 + n] = v.z;
            Bt[(kg * 4 + 3) * 64 + n] = v.w;
        }
        __syncthreads();

        #pragma unroll
        for (int kk = 0; kk < 16; kk++) {
            float a[2];
            #pragma unroll
            for (int i = 0; i < 2; i++) a[i] = At[kk * 128 + rh + tx + 32 * i];
            // B frag: 16 floats as 4 LDS.128 -> 8 packed u64
            u64 b[8];
            #pragma unroll
            for (int q = 0; q < 4; q++) {
                float4 bv = *reinterpret_cast<const float4*>(&Bt[kk * 64 + cb + q * 4]);
                b[q * 2 + 0] = *reinterpret_cast<const u64*>(&bv.x);
                b[q * 2 + 1] = *reinterpret_cast<const u64*>(&bv.z);
            }
            #pragma unroll
            for (int i = 0; i < 2; i++) {
                u64 ar = rep2(a[i]);
                #pragma unroll
                for (int j2 = 0; j2 < 8; j2++) fma2(accP[i][j2], ar, b[j2]);
            }
        }
    }

    // relu -> Yt[k][m]
    __syncthreads();
#pragma unroll
    for (int i = 0; i < 2; i++)
#pragma unroll
        for (int j2 = 0; j2 < 8; j2++) {
            float2 p = unpack2(accP[i][j2]);
            Yt[(cb + j2 * 2 + 0) * 128 + rh + tx + 32 * i] = fmaxf(p.x, 0.f);
            Yt[(cb + j2 * 2 + 1) * 128 + rh + tx + 32 * i] = fmaxf(p.y, 0.f);
            accP[i][j2] = 0ull;
        }
    __syncthreads();

    // ======================= phase 2: K = 64 =======================
#pragma unroll 8
    for (int kk = 0; kk < 64; kk++) {
        float a[2];
        #pragma unroll
        for (int i = 0; i < 2; i++) a[i] = Yt[kk * 128 + rh + tx + 32 * i];
        u64 b[8];
        #pragma unroll
        for (int q = 0; q < 4; q++) {
            float4 bv = *reinterpret_cast<const float4*>(&W2t[kk * 64 + cb + q * 4]);
            b[q * 2 + 0] = *reinterpret_cast<const u64*>(&bv.x);
            b[q * 2 + 1] = *reinterpret_cast<const u64*>(&bv.z);
        }
        #pragma unroll
        for (int i = 0; i < 2; i++) {
            u64 ar = rep2(a[i]);
            #pragma unroll
            for (int j2 = 0; j2 < 8; j2++) fma2(accP[i][j2], ar, b[j2]);
        }
    }

    // ---- epilogue: mask by deg, write out ----
#pragma unroll
    for (int i = 0; i < 2; i++) {
        int n = base + rh + tx + 32 * i;
        if (n >= N_NODES) continue;
        bool has = (g_count[n] > 0);
        #pragma unroll
        for (int q = 0; q < 4; q++) {
            float4 wv;
            if (has) {
                float2 p0 = unpack2(accP[i][q * 2 + 0]);
                float2 p1 = unpack2(accP[i][q * 2 + 1]);
                wv = make_float4(p0.x, p0.y, p1.x, p1.y);
            } else {
                wv = *reinterpret_cast<const float4*>(
                    h + (size_t)n * HIDDEN + cb + q * 4);
            }
            *reinterpret_cast<float4*>(
                out + (size_t)n * HIDDEN + cb + q * 4) = wv;
        }
    }
}

// ---------------------------------------------------------------------------
extern "C" void kernel_launch(void* const* d_in, const int* in_sizes, int n_in,
                              void* d_out, int out_size)
{
    const float* h   = (const float*)d_in[0];
    const float* nf  = (const float*)d_in[1];
    const float* ef  = (const float*)d_in[2];
    const int*   src = (const int*)d_in[3];
    const int*   dst = (const int*)d_in[4];
    const float* W1  = (const float*)d_in[5];
    const float* W2  = (const float*)d_in[6];
    float*       out = (float*)d_out;

    zero_kernel<<<(N_NODES / 4 + 255) / 256, 256>>>();
    scatter_kernel<<<(N_EDGES + 255) / 256, 256>>>(src, dst);
    gather_kernel<<<(N_NODES * 32 + 255) / 256, 256>>>(h, ef);

    cudaFuncSetAttribute(fused_node_kernel,
                         cudaFuncAttributeMaxDynamicSharedMemorySize,
                         FUSED_SMEM_FLOATS * sizeof(float));
    const int blocks = (N_NODES + 127) / 128;   // 391
    fused_node_kernel<<<blocks, 256, FUSED_SMEM_FLOATS * sizeof(float)>>>(
        h, nf, W1, W2, out);
}

// round 9
// speedup vs baseline: 1.1290x; 1.0449x over previous
#include <cuda_runtime.h>

#define N_NODES 50000
#define N_EDGES 800000
#define HIDDEN 64
#define NODE_DIM 32
#define EDGE_DIM 16
#define CAP 96

// acc row per node (80 floats): [0:16)=sum(ef), [16:80)=sum(h[src])
__device__ __align__(16) float g_acc[(size_t)N_NODES * 80];
__device__ int   g_count[N_NODES];
__device__ int   g_ovf_cnt;
__device__ __align__(16) int2 g_ell[(size_t)N_NODES * CAP];  // (src, edge)
__device__ int3  g_ovf[N_EDGES];

typedef unsigned long long u64;

__device__ __forceinline__ void fma2(u64& d, u64 a, u64 b) {
    asm("fma.rn.f32x2 %0, %1, %2, %0;" : "+l"(d) : "l"(a), "l"(b));
}
__device__ __forceinline__ u64 rep2(float x) {
    u64 r;
    asm("mov.b64 %0, {%1, %1};" : "=l"(r) : "f"(x));
    return r;
}
__device__ __forceinline__ float2 unpack2(u64 v) {
    float2 p;
    asm("mov.b64 {%0, %1}, %2;" : "=f"(p.x), "=f"(p.y) : "l"(v));
    return p;
}

// ---------------------------------------------------------------------------
__global__ void zero_kernel() {
    int i = blockIdx.x * blockDim.x + threadIdx.x;
    const int CNT4 = N_NODES / 4;
    if (i < CNT4) reinterpret_cast<int4*>(g_count)[i] = make_int4(0, 0, 0, 0);
    if (i == 0) g_ovf_cnt = 0;
}

// ---------------------------------------------------------------------------
__global__ void __launch_bounds__(256) scatter_kernel(
    const int* __restrict__ src, const int* __restrict__ dst)
{
    int e = blockIdx.x * 256 + threadIdx.x;
    if (e >= N_EDGES) return;
    int d = dst[e];
    int s = src[e];
    int pos = atomicAdd(&g_count[d], 1);
    if (pos < CAP) {
        g_ell[(size_t)d * CAP + pos] = make_int2(s, e);
    } else {
        int o = atomicAdd(&g_ovf_cnt, 1);
        g_ovf[o] = make_int3(d, s, e);
    }
}

// ---------------------------------------------------------------------------
// gather_ef: 4-lane group per node. Lane l owns ef float4 chunk l.
// Writes g_acc[n*80 + 0..16).
// ---------------------------------------------------------------------------
__global__ void __launch_bounds__(256) gather_ef_kernel(
    const float* __restrict__ ef)
{
    int g = (blockIdx.x * 256 + threadIdx.x) >> 2;
    int l = threadIdx.x & 3;
    if (g >= N_NODES) return;
    int cnt_raw = g_count[g];
    if (cnt_raw == 0) return;
    int cnt = min(cnt_raw, CAP);

    const int4* __restrict__ eb4 = reinterpret_cast<const int4*>(g_ell + (size_t)g * CAP);
    float4 a = make_float4(0.f, 0.f, 0.f, 0.f);

    int j = 0;
    for (; j + 4 <= cnt; j += 4) {
        int4 p0 = eb4[(j >> 1) + 0];         // (s0,e0,s1,e1)
        int4 p1 = eb4[(j >> 1) + 1];         // (s2,e2,s3,e3)
        float4 v0 = *reinterpret_cast<const float4*>(ef + (size_t)p0.y * EDGE_DIM + l * 4);
        float4 v1 = *reinterpret_cast<const float4*>(ef + (size_t)p0.w * EDGE_DIM + l * 4);
        float4 v2 = *reinterpret_cast<const float4*>(ef + (size_t)p1.y * EDGE_DIM + l * 4);
        float4 v3 = *reinterpret_cast<const float4*>(ef + (size_t)p1.w * EDGE_DIM + l * 4);
        a.x += v0.x + v1.x + v2.x + v3.x;
        a.y += v0.y + v1.y + v2.y + v3.y;
        a.z += v0.z + v1.z + v2.z + v3.z;
        a.w += v0.w + v1.w + v2.w + v3.w;
    }
    for (; j < cnt; j++) {
        int e = g_ell[(size_t)g * CAP + j].y;
        float4 v = *reinterpret_cast<const float4*>(ef + (size_t)e * EDGE_DIM + l * 4);
        a.x += v.x; a.y += v.y; a.z += v.z; a.w += v.w;
    }
    if (cnt_raw > CAP) {                     // exact fallback; practically never taken
        int ovf = g_ovf_cnt;
        for (int i = 0; i < ovf; i++) {
            int3 t = g_ovf[i];
            if (t.x == g) {
                float4 v = *reinterpret_cast<const float4*>(ef + (size_t)t.z * EDGE_DIM + l * 4);
                a.x += v.x; a.y += v.y; a.z += v.z; a.w += v.w;
            }
        }
    }
    *reinterpret_cast<float4*>(g_acc + (size_t)g * 80 + l * 4) = a;
}

// ---------------------------------------------------------------------------
// gather_h: 16-lane group per node. Lane l owns h float4 chunk l — each edge
// is one fully-dense 256B row read by the group. Writes g_acc[n*80 + 16..80).
// ---------------------------------------------------------------------------
__global__ void __launch_bounds__(256) gather_h_kernel(
    const float* __restrict__ h)
{
    int g = (blockIdx.x * 256 + threadIdx.x) >> 4;
    int l = threadIdx.x & 15;
    if (g >= N_NODES) return;
    int cnt_raw = g_count[g];
    if (cnt_raw == 0) return;
    int cnt = min(cnt_raw, CAP);

    const int4* __restrict__ eb4 = reinterpret_cast<const int4*>(g_ell + (size_t)g * CAP);
    float4 a = make_float4(0.f, 0.f, 0.f, 0.f);

    int j = 0;
    for (; j + 4 <= cnt; j += 4) {
        int4 p0 = eb4[(j >> 1) + 0];
        int4 p1 = eb4[(j >> 1) + 1];
        float4 v0 = *reinterpret_cast<const float4*>(h + (size_t)p0.x * HIDDEN + l * 4);
        float4 v1 = *reinterpret_cast<const float4*>(h + (size_t)p0.z * HIDDEN + l * 4);
        float4 v2 = *reinterpret_cast<const float4*>(h + (size_t)p1.x * HIDDEN + l * 4);
        float4 v3 = *reinterpret_cast<const float4*>(h + (size_t)p1.z * HIDDEN + l * 4);
        a.x += v0.x + v1.x + v2.x + v3.x;
        a.y += v0.y + v1.y + v2.y + v3.y;
        a.z += v0.z + v1.z + v2.z + v3.z;
        a.w += v0.w + v1.w + v2.w + v3.w;
    }
    for (; j < cnt; j++) {
        int s = g_ell[(size_t)g * CAP + j].x;
        float4 v = *reinterpret_cast<const float4*>(h + (size_t)s * HIDDEN + l * 4);
        a.x += v.x; a.y += v.y; a.z += v.z; a.w += v.w;
    }
    if (cnt_raw > CAP) {                     // exact fallback
        int ovf = g_ovf_cnt;
        for (int i = 0; i < ovf; i++) {
            int3 t = g_ovf[i];
            if (t.x == g) {
                float4 v = *reinterpret_cast<const float4*>(h + (size_t)t.y * HIDDEN + l * 4);
                a.x += v.x; a.y += v.y; a.z += v.z; a.w += v.w;
            }
        }
    }
    *reinterpret_cast<float4*>(g_acc + (size_t)g * 80 + 16 + l * 4) = a;
}

// ---------------------------------------------------------------------------
// Fused node kernel — 256 threads, M=128 tile, 2x16 microtile, f32x2 FMAs,
// DOUBLE-BUFFERED K-chunks (reg-staged): LDG(kc+1) overlaps compute(kc).
// Smem 48KB:
//   stage0 A[16][128]=2048 @0,  B[16][64]=1024 @2048
//   stage1 A @3072,            B @5120        (stages end at 6144)
//   Yt[64][128]=8192 @0 (aliases stages, used after final barrier)
//   W2t[64][64]=4096 @8192
// ---------------------------------------------------------------------------
#define FUSED_SMEM_FLOATS 12288   // 49,152 bytes

__device__ __forceinline__ float4 load_z(
    const float* __restrict__ nf, int nrow, bool valid, float degf, int gk)
{
    float4 v = make_float4(0.f, 0.f, 0.f, 0.f);
    if (valid) {
        if (gk < 32) {
            v = *reinterpret_cast<const float4*>(nf + (size_t)nrow * 32 + gk);
        } else if (gk < 64) {
            v = *reinterpret_cast<const float4*>(nf + (size_t)nrow * 32 + gk - 32);
            v.x *= degf; v.y *= degf; v.z *= degf; v.w *= degf;
        } else {
            size_t off = (size_t)nrow * 80 + ((gk < 80) ? (gk - 64) : (16 + (gk - 80)));
            v = *reinterpret_cast<const float4*>(g_acc + off);
        }
    }
    return v;
}

__global__ void __launch_bounds__(256, 3) fused_node_kernel(
    const float* __restrict__ h, const float* __restrict__ nf,
    const float* __restrict__ W1, const float* __restrict__ W2,
    float* __restrict__ out)
{
    extern __shared__ float sm[];
    float* Yt  = sm;                 // [64][128], aliases both stages
    float* W2t = sm + 8192;          // [64][64]

    const int tid   = threadIdx.x;
    const int tx    = tid & 31;
    const int w     = tid >> 5;
    const int rh    = (w >> 2) * 64;
    const int cb    = (w & 3) * 16;
    const int base  = blockIdx.x * 128;

    // one-time: W2 -> W2t[k][n] (consumed only in phase 2, after barriers)
    {
        int n = tid & 63, kp = tid >> 6;
        #pragma unroll
        for (int r = 0; r < 4; r++) {
            int kf4 = kp + r * 4;
            float4 v = *reinterpret_cast<const float4*>(W2 + (size_t)n * 64 + kf4 * 4);
            W2t[(kf4 * 4 + 0) * 64 + n] = v.x;
            W2t[(kf4 * 4 + 1) * 64 + n] = v.y;
            W2t[(kf4 * 4 + 2) * 64 + n] = v.z;
            W2t[(kf4 * 4 + 3) * 64 + n] = v.w;
        }
    }

    u64 accP[2][8];
#pragma unroll
    for (int i = 0; i < 2; i++)
#pragma unroll
        for (int j = 0; j < 8; j++) accP[i][j] = 0ull;

    // loader roles
    const int rowA = tid & 127;
    const int kpA  = tid >> 7;            // 0/1: which 8-k half this thread loads
    const int nrow = base + rowA;
    const bool valid = (nrow < N_NODES);
    const float degf = valid ? (float)g_count[nrow] : 0.f;
    const int nB = tid & 63, kgB = tid >> 6;   // B loader: row nB, k4-group kgB

    float4 ra0, ra1, rb;

    // ---- prologue: chunk 0 -> regs -> stage 0 ----
    ra0 = load_z(nf, nrow, valid, degf, (kpA * 2 + 0) * 4);
    ra1 = load_z(nf, nrow, valid, degf, (kpA * 2 + 1) * 4);
    rb  = *reinterpret_cast<const float4*>(W1 + (size_t)nB * 144 + kgB * 4);
    {
        float* As = sm; float* Bs = sm + 2048;
        int g0 = kpA * 2;
        As[(g0 * 4 + 0) * 128 + rowA] = ra0.x;
        As[(g0 * 4 + 1) * 128 + rowA] = ra0.y;
        As[(g0 * 4 + 2) * 128 + rowA] = ra0.z;
        As[(g0 * 4 + 3) * 128 + rowA] = ra0.w;
        As[((g0 + 1) * 4 + 0) * 128 + rowA] = ra1.x;
        As[((g0 + 1) * 4 + 1) * 128 + rowA] = ra1.y;
        As[((g0 + 1) * 4 + 2) * 128 + rowA] = ra1.z;
        As[((g0 + 1) * 4 + 3) * 128 + rowA] = ra1.w;
        Bs[(kgB * 4 + 0) * 64 + nB] = rb.x;
        Bs[(kgB * 4 + 1) * 64 + nB] = rb.y;
        Bs[(kgB * 4 + 2) * 64 + nB] = rb.z;
        Bs[(kgB * 4 + 3) * 64 + nB] = rb.w;
    }
    __syncthreads();

    // ======================= phase 1: K = 144, 9 chunks =======================
    for (int kc = 0; kc < 9; kc++) {
        // issue next chunk's LDGs first (latency overlapped with compute)
        if (kc < 8) {
            int k0n = (kc + 1) * 16;
            ra0 = load_z(nf, nrow, valid, degf, k0n + (kpA * 2 + 0) * 4);
            ra1 = load_z(nf, nrow, valid, degf, k0n + (kpA * 2 + 1) * 4);
            rb  = *reinterpret_cast<const float4*>(W1 + (size_t)nB * 144 + k0n + kgB * 4);
        }

        const float* As = (kc & 1) ? (sm + 3072) : sm;
        const float* Bs = (kc & 1) ? (sm + 5120) : (sm + 2048);
        #pragma unroll
        for (int kk = 0; kk < 16; kk++) {
            float a[2];
            #pragma unroll
            for (int i = 0; i < 2; i++) a[i] = As[kk * 128 + rh + tx + 32 * i];
            u64 b[8];
            #pragma unroll
            for (int q = 0; q < 4; q++) {
                float4 bv = *reinterpret_cast<const float4*>(&Bs[kk * 64 + cb + q * 4]);
                b[q * 2 + 0] = *reinterpret_cast<const u64*>(&bv.x);
                b[q * 2 + 1] = *reinterpret_cast<const u64*>(&bv.z);
            }
            #pragma unroll
            for (int i = 0; i < 2; i++) {
                u64 ar = rep2(a[i]);
                #pragma unroll
                for (int j2 = 0; j2 < 8; j2++) fma2(accP[i][j2], ar, b[j2]);
            }
        }

        if (kc < 8) {
            float* An = (kc & 1) ? sm : (sm + 3072);
            float* Bn = (kc & 1) ? (sm + 2048) : (sm + 5120);
            int g0 = kpA * 2;
            An[(g0 * 4 + 0) * 128 + rowA] = ra0.x;
            An[(g0 * 4 + 1) * 128 + rowA] = ra0.y;
            An[(g0 * 4 + 2) * 128 + rowA] = ra0.z;
            An[(g0 * 4 + 3) * 128 + rowA] = ra0.w;
            An[((g0 + 1) * 4 + 0) * 128 + rowA] = ra1.x;
            An[((g0 + 1) * 4 + 1) * 128 + rowA] = ra1.y;
            An[((g0 + 1) * 4 + 2) * 128 + rowA] = ra1.z;
            An[((g0 + 1) * 4 + 3) * 128 + rowA] = ra1.w;
            Bn[(kgB * 4 + 0) * 64 + nB] = rb.x;
            Bn[(kgB * 4 + 1) * 64 + nB] = rb.y;
            Bn[(kgB * 4 + 2) * 64 + nB] = rb.z;
            Bn[(kgB * 4 + 3) * 64 + nB] = rb.w;
        }
        __syncthreads();
    }

    // relu -> Yt[k][m] (Yt aliases stages; last stage reads completed at barrier)
#pragma unroll
    for (int i = 0; i < 2; i++)
#pragma unroll
        for (int j2 = 0; j2 < 8; j2++) {
            float2 p = unpack2(accP[i][j2]);
            Yt[(cb + j2 * 2 + 0) * 128 + rh + tx + 32 * i] = fmaxf(p.x, 0.f);
            Yt[(cb + j2 * 2 + 1) * 128 + rh + tx + 32 * i] = fmaxf(p.y, 0.f);
            accP[i][j2] = 0ull;
        }
    __syncthreads();

    // ======================= phase 2: K = 64 =======================
#pragma unroll 8
    for (int kk = 0; kk < 64; kk++) {
        float a[2];
        #pragma unroll
        for (int i = 0; i < 2; i++) a[i] = Yt[kk * 128 + rh + tx + 32 * i];
        u64 b[8];
        #pragma unroll
        for (int q = 0; q < 4; q++) {
            float4 bv = *reinterpret_cast<const float4*>(&W2t[kk * 64 + cb + q * 4]);
            b[q * 2 + 0] = *reinterpret_cast<const u64*>(&bv.x);
            b[q * 2 + 1] = *reinterpret_cast<const u64*>(&bv.z);
        }
        #pragma unroll
        for (int i = 0; i < 2; i++) {
            u64 ar = rep2(a[i]);
            #pragma unroll
            for (int j2 = 0; j2 < 8; j2++) fma2(accP[i][j2], ar, b[j2]);
        }
    }

    // ---- epilogue: mask by deg ----
#pragma unroll
    for (int i = 0; i < 2; i++) {
        int n = base + rh + tx + 32 * i;
        if (n >= N_NODES) continue;
        bool has = (g_count[n] > 0);
        #pragma unroll
        for (int q = 0; q < 4; q++) {
            float4 wv;
            if (has) {
                float2 p0 = unpack2(accP[i][q * 2 + 0]);
                float2 p1 = unpack2(accP[i][q * 2 + 1]);
                wv = make_float4(p0.x, p0.y, p1.x, p1.y);
            } else {
                wv = *reinterpret_cast<const float4*>(h + (size_t)n * HIDDEN + cb + q * 4);
            }
            *reinterpret_cast<float4*>(out + (size_t)n * HIDDEN + cb + q * 4) = wv;
        }
    }
}

// ---------------------------------------------------------------------------
extern "C" void kernel_launch(void* const* d_in, const int* in_sizes, int n_in,
                              void* d_out, int out_size)
{
    const float* h   = (const float*)d_in[0];
    const float* nf  = (const float*)d_in[1];
    const float* ef  = (const float*)d_in[2];
    const int*   src = (const int*)d_in[3];
    const int*   dst = (const int*)d_in[4];
    const float* W1  = (const float*)d_in[5];
    const float* W2  = (const float*)d_in[6];
    float*       out = (float*)d_out;

    zero_kernel<<<(N_NODES / 4 + 255) / 256, 256>>>();
    scatter_kernel<<<(N_EDGES + 255) / 256, 256>>>(src, dst);

    gather_ef_kernel<<<(N_NODES * 4 + 255) / 256, 256>>>(ef);
    gather_h_kernel<<<(N_NODES * 16 + 255) / 256, 256>>>(h);

    cudaFuncSetAttribute(fused_node_kernel,
                         cudaFuncAttributeMaxDynamicSharedMemorySize,
                         FUSED_SMEM_FLOATS * sizeof(float));
    const int blocks = (N_NODES + 127) / 128;   // 391
    fused_node_kernel<<<blocks, 256, FUSED_SMEM_FLOATS * sizeof(float)>>>(
        h, nf, W1, W2, out);
}